// round 2
// baseline (speedup 1.0000x reference)
#include <cuda_runtime.h>

#define NTOK   4096
#define PDIM   128
#define HEADS  4
#define EDIM   32
#define NSEGS  32
#define SROWS  256     // max segment rows held in SMEM (counts ~128 +- 30 for this input)
#define NWARPS 8
#define ZBLK   4
#define QSCALE 0.17677669529663687f  // 1/sqrt(32)
#define NEGINF (-3.0e38f)

// Scratch (no allocations allowed): Q, K, V projections + segment index lists
__device__ float g_QKV[3][NTOK * PDIM];
__device__ int   g_idx[NTOK];
__device__ int   g_off[NSEGS + 1];
__device__ int   g_cnt[NSEGS];

// ---------------------------------------------------------------------------
// QKV projection: out[n][p] = inp[n][:] @ W[:][p] + b[p]
// grid (NTOK/64, 3)  block 256  dyn smem = 64*128*4 + 128*128*4 = 98304 B
// ---------------------------------------------------------------------------
__global__ void qkv_kernel(const float* __restrict__ inp,
                           const float* __restrict__ Wq, const float* __restrict__ bq,
                           const float* __restrict__ Wk, const float* __restrict__ bk,
                           const float* __restrict__ Wv, const float* __restrict__ bv)
{
    extern __shared__ float sm[];
    float* As = sm;                 // 64 x 128
    float* Bs = sm + 64 * PDIM;     // 128 x 128

    const int which = blockIdx.y;
    const float* W = (which == 0) ? Wq : (which == 1) ? Wk : Wv;
    const float* b = (which == 0) ? bq : (which == 1) ? bk : bv;
    float* out = g_QKV[which];

    const int row0 = blockIdx.x * 64;
    const int tid  = threadIdx.x;

    // cooperative loads (vectorized)
    const float4* inp4 = (const float4*)(inp + row0 * PDIM);
    float4* As4 = (float4*)As;
    for (int i = tid; i < 64 * PDIM / 4; i += 256) As4[i] = inp4[i];
    const float4* W4 = (const float4*)W;
    float4* Bs4 = (float4*)Bs;
    for (int i = tid; i < PDIM * PDIM / 4; i += 256) Bs4[i] = W4[i];
    __syncthreads();

    const int tx = tid & 31;   // cols tx*4 .. tx*4+3
    const int ty = tid >> 5;   // rows ty*8 .. ty*8+7

    float acc[8][4];
#pragma unroll
    for (int i = 0; i < 8; i++)
#pragma unroll
        for (int j = 0; j < 4; j++) acc[i][j] = 0.f;

#pragma unroll 4
    for (int k = 0; k < PDIM; k++) {
        float4 bv4 = Bs4[k * 32 + tx];
#pragma unroll
        for (int i = 0; i < 8; i++) {
            float a = As[(ty * 8 + i) * PDIM + k];   // warp-broadcast
            acc[i][0] += a * bv4.x;
            acc[i][1] += a * bv4.y;
            acc[i][2] += a * bv4.z;
            acc[i][3] += a * bv4.w;
        }
    }

    float4 b4 = ((const float4*)b)[tx];
    float4* out4 = (float4*)out;
#pragma unroll
    for (int i = 0; i < 8; i++) {
        int row = row0 + ty * 8 + i;
        float4 r;
        r.x = acc[i][0] + b4.x;
        r.y = acc[i][1] + b4.y;
        r.z = acc[i][2] + b4.z;
        r.w = acc[i][3] + b4.w;
        out4[row * 32 + tx] = r;
    }
}

// ---------------------------------------------------------------------------
// Deterministic stable counting sort of token indices by segment
// ---------------------------------------------------------------------------
__global__ void zero_kernel() {
    if (threadIdx.x < NSEGS) g_cnt[threadIdx.x] = 0;
}

__global__ void count_kernel(const int* __restrict__ pos) {
    int i = blockIdx.x * blockDim.x + threadIdx.x;
    if (i < NTOK) atomicAdd(&g_cnt[pos[i]], 1);
}

__global__ void scan_kernel() {   // 1 warp: exclusive scan of 32 counts
    int lane = threadIdx.x;
    int v = (lane < NSEGS) ? g_cnt[lane] : 0;
    int s = v;
#pragma unroll
    for (int d = 1; d < 32; d <<= 1) {
        int o = __shfl_up_sync(0xffffffffu, s, d);
        if (lane >= d) s += o;
    }
    if (lane < NSEGS) g_off[lane + 1] = s;
    if (lane == 0)    g_off[0] = 0;
}

// rank of token i within its segment = #{j<i : pos[j]==pos[i]}  (stable, deterministic)
__global__ void scatter_kernel(const int* __restrict__ pos) {
    int i = blockIdx.x * blockDim.x + threadIdx.x;
    if (i >= NTOK) return;
    int s = pos[i];
    int rank = 0;
    const int4* p4 = (const int4*)pos;
    int j = 0;
    int lim4 = i & ~3;
    for (; j < lim4; j += 4) {
        int4 v = __ldg(&p4[j >> 2]);
        rank += (v.x == s) + (v.y == s) + (v.z == s) + (v.w == s);
    }
    for (; j < i; j++) rank += (__ldg(&pos[j]) == s);
    g_idx[g_off[s] + rank] = i;
}

// ---------------------------------------------------------------------------
// Per-segment per-head attention.
// grid (NSEGS, HEADS, ZBLK)  block 256 (8 warps)  dyn smem 74752 B
// SMEM: KT [EDIM][SROWS] (transposed K), Vs [SROWS][EDIM], Ps [NWARPS][SROWS],
//       Qs [NWARPS][EDIM]
// Each warp handles one query at a time (two-pass softmax over segment keys).
// ---------------------------------------------------------------------------
__global__ void attn_kernel(float* __restrict__ out)
{
    extern __shared__ float sm[];
    float* KT = sm;                             // EDIM * SROWS
    float* Vs = KT + EDIM * SROWS;              // SROWS * EDIM
    float* Ps = Vs + SROWS * EDIM;              // NWARPS * SROWS
    float* Qs = Ps + NWARPS * SROWS;            // NWARPS * EDIM

    const int seg = blockIdx.x, h = blockIdx.y, z = blockIdx.z;
    const int off   = g_off[seg];
    const int count = g_cnt[seg];
    const int tid = threadIdx.x, lane = tid & 31, w = tid >> 5;

    const float* Q = g_QKV[0];
    const float* K = g_QKV[1];
    const float* V = g_QKV[2];

    if (count <= SROWS) {
        // cooperative gather of segment K (transposed) and V into SMEM
        for (int i = tid; i < count * 8; i += NWARPS * 32) {
            int r = i >> 3, c = i & 7;
            int t = g_idx[off + r];
            float4 kf = *(const float4*)(K + t * PDIM + h * EDIM + c * 4);
            KT[(c * 4 + 0) * SROWS + r] = kf.x;
            KT[(c * 4 + 1) * SROWS + r] = kf.y;
            KT[(c * 4 + 2) * SROWS + r] = kf.z;
            KT[(c * 4 + 3) * SROWS + r] = kf.w;
            ((float4*)Vs)[r * 8 + c] = *(const float4*)(V + t * PDIM + h * EDIM + c * 4);
        }
        __syncthreads();

        float* p  = Ps + w * SROWS;
        float* qs = Qs + w * EDIM;

        for (int qi = z * NWARPS + w; qi < count; qi += ZBLK * NWARPS) {
            int t = g_idx[off + qi];
            qs[lane] = Q[t * PDIM + h * EDIM + lane] * QSCALE;
            __syncwarp();

            // q into registers (kills smem reloads in the hot loop)
            float qr[EDIM];
#pragma unroll
            for (int e = 0; e < EDIM; e++) qr[e] = qs[e];

            // pass 1: scores, lane = key (KT reads conflict-free)
            float mloc = NEGINF;
            for (int j = lane; j < count; j += 32) {
                float s = 0.f;
#pragma unroll
                for (int e = 0; e < EDIM; e++) s += qr[e] * KT[e * SROWS + j];
                p[j] = s;
                mloc = fmaxf(mloc, s);
            }
#pragma unroll
            for (int d = 16; d; d >>= 1)
                mloc = fmaxf(mloc, __shfl_xor_sync(0xffffffffu, mloc, d));

            // pass 2: exp + sum
            float lsum = 0.f;
            for (int j = lane; j < count; j += 32) {
                float e = __expf(p[j] - mloc);
                p[j] = e;
                lsum += e;
            }
#pragma unroll
            for (int d = 16; d; d >>= 1)
                lsum += __shfl_xor_sync(0xffffffffu, lsum, d);
            float inv = 1.f / lsum;
            __syncwarp();

            // pass 3: accumulate, lane = e (p broadcast, Vs conflict-free)
            float acc = 0.f;
            for (int j = 0; j < count; j++)
                acc += p[j] * Vs[j * EDIM + lane];

            out[t * PDIM + h * EDIM + lane] = acc * inv;
            __syncwarp();   // protect p before next query reuses it
        }
    } else {
        // fallback (never taken for this input): stream keys from global, online softmax
        for (int qi = z * NWARPS + w; qi < count; qi += ZBLK * NWARPS) {
            int t = g_idx[off + qi];
            float q = Q[t * PDIM + h * EDIM + lane] * QSCALE;
            float m = NEGINF, l = 0.f, acc = 0.f;
            for (int j = 0; j < count; j++) {
                int tj = g_idx[off + j];
                float s = q * K[tj * PDIM + h * EDIM + lane];
#pragma unroll
                for (int d = 16; d; d >>= 1)
                    s += __shfl_xor_sync(0xffffffffu, s, d);
                float mn  = fmaxf(m, s);
                float cor = __expf(m - mn);
                float pj  = __expf(s - mn);
                l   = l * cor + pj;
                acc = acc * cor + pj * V[tj * PDIM + h * EDIM + lane];
                m = mn;
            }
            out[t * PDIM + h * EDIM + lane] = acc / l;
        }
    }
}

// ---------------------------------------------------------------------------
extern "C" void kernel_launch(void* const* d_in, const int* in_sizes, int n_in,
                              void* d_out, int out_size)
{
    const float* inp = (const float*)d_in[0];
    const int*   pos = (const int*)  d_in[1];
    const float* Wq  = (const float*)d_in[2];
    const float* bq  = (const float*)d_in[3];
    const float* Wk  = (const float*)d_in[4];
    const float* bk  = (const float*)d_in[5];
    const float* Wv  = (const float*)d_in[6];
    const float* bv  = (const float*)d_in[7];
    float* out = (float*)d_out;

    const int qkv_smem  = (64 * PDIM + PDIM * PDIM) * 4;                       // 98304
    const int attn_smem = (EDIM * SROWS + SROWS * EDIM + NWARPS * SROWS
                           + NWARPS * EDIM) * 4;                               // 74752

    cudaFuncSetAttribute(qkv_kernel,  cudaFuncAttributeMaxDynamicSharedMemorySize, qkv_smem);
    cudaFuncSetAttribute(attn_kernel, cudaFuncAttributeMaxDynamicSharedMemorySize, attn_smem);

    qkv_kernel<<<dim3(NTOK / 64, 3), 256, qkv_smem>>>(inp, Wq, bq, Wk, bk, Wv, bv);
    zero_kernel<<<1, 32>>>();
    count_kernel<<<NTOK / 256, 256>>>(pos);
    scan_kernel<<<1, 32>>>();
    scatter_kernel<<<NTOK / 256, 256>>>(pos);
    attn_kernel<<<dim3(NSEGS, HEADS, ZBLK), NWARPS * 32, attn_smem>>>(out);
}

// round 3
// speedup vs baseline: 2.9070x; 2.9070x over previous
#include <cuda_runtime.h>

#define NTOK   4096
#define PDIM   128
#define HEADS  4
#define EDIM   32
#define NSEGS  32
#define KCAP   192     // max keys per segment handled by the fast path (mu=128, sd=11)
#define QT     64      // queries per attention block
#define QTILES 3       // covers up to 192 queries in the fast path
#define SSTR   66      // S row stride (floats): even (float2 ok), 2-way-conflict softmax
#define QSCALE 0.17677669529663687f  // 1/sqrt(32)
#define NEGINF (-3.0e38f)

// Scratch (no allocations allowed)
__device__ float g_QKV[3][NTOK * PDIM];
__device__ int   g_idx[NTOK];
__device__ int   g_off[NSEGS + 1];
__device__ int   g_cnt[NSEGS];

// ---------------------------------------------------------------------------
// f32x2 packed helpers (sm_103a): 2x fp32 FMA throughput via PTX-only FFMA2
// ---------------------------------------------------------------------------
__device__ __forceinline__ unsigned long long f2pk(float lo, float hi) {
    unsigned long long r;
    asm("mov.b64 %0, {%1, %2};" : "=l"(r) : "f"(lo), "f"(hi));
    return r;
}
__device__ __forceinline__ unsigned long long ffma2(unsigned long long a,
                                                    unsigned long long b,
                                                    unsigned long long c) {
    unsigned long long d;
    asm("fma.rn.f32x2 %0, %1, %2, %3;" : "=l"(d) : "l"(a), "l"(b), "l"(c));
    return d;
}
__device__ __forceinline__ void f2un(unsigned long long v, float& lo, float& hi) {
    asm("mov.b64 {%0, %1}, %2;" : "=f"(lo), "=f"(hi) : "l"(v));
}

// ---------------------------------------------------------------------------
// Fused O(N) deterministic stable sort-by-segment (one block, 256 threads).
// Groups of 32 tokens; per-(seg,group) histogram via match_any; block scan
// of 4096 counts in (seg-major, group-minor) order; rank-scatter.
// ---------------------------------------------------------------------------
__device__ void sort_block(const int* __restrict__ pos, int* sm) {
    int* spos    = sm;            // 4096
    int* hist    = sm + 4096;     // 4096  (hist[s*128 + g])
    int* warptot = sm + 8192;     // 8

    const int tid = threadIdx.x, lane = tid & 31, w = tid >> 5;

    // cache pos + zero hist
    const int4* pos4 = (const int4*)pos;
    int4 z4 = make_int4(0, 0, 0, 0);
    for (int i = tid; i < NTOK / 4; i += 256) {
        ((int4*)spos)[i] = pos4[i];
        ((int4*)hist)[i] = z4;
    }
    __syncthreads();

    // Phase A: per-group histograms
    for (int g = w; g < 128; g += 8) {
        int s = spos[g * 32 + lane];
        unsigned mask = __match_any_sync(0xffffffffu, s);
        int leader = __ffs(mask) - 1;
        if (lane == leader) hist[s * 128 + g] = __popc(mask);
    }
    __syncthreads();

    // Phase B: exclusive scan of hist[0..4095] (16 values per thread)
    int base = tid * 16;
    int loc[16];
    int run = 0;
#pragma unroll
    for (int i = 0; i < 16; i++) { loc[i] = run; run += hist[base + i]; }
    int s = run;
#pragma unroll
    for (int d = 1; d < 32; d <<= 1) {
        int o = __shfl_up_sync(0xffffffffu, s, d);
        if (lane >= d) s += o;
    }
    int excl = s - run;
    if (lane == 31) warptot[w] = s;
    __syncthreads();
    if (tid == 0) {
        int a = 0;
#pragma unroll
        for (int i = 0; i < 8; i++) { int t = warptot[i]; warptot[i] = a; a += t; }
    }
    __syncthreads();
    int offt = warptot[w] + excl;
#pragma unroll
    for (int i = 0; i < 16; i++) hist[base + i] = offt + loc[i];
    __syncthreads();

    // segment offsets + counts
    if (tid < NSEGS) {
        int o   = hist[tid * 128];
        int nxt = (tid == NSEGS - 1) ? NTOK : hist[(tid + 1) * 128];
        g_off[tid] = o;
        g_cnt[tid] = nxt - o;
        if (tid == 0) g_off[NSEGS] = NTOK;
    }

    // Phase C: stable rank-scatter
    for (int g = w; g < 128; g += 8) {
        int tok = g * 32 + lane;
        int sg = spos[tok];
        unsigned mask = __match_any_sync(0xffffffffu, sg);
        int rank = __popc(mask & ((1u << lane) - 1u));
        g_idx[hist[sg * 128 + g] + rank] = tok;
    }
}

// ---------------------------------------------------------------------------
// QKV projection (f32x2) + fused sort block.
// grid (65, 6): x<64 -> 64-row x 64-col GEMM tiles (y = mat*2 + colhalf),
//               x==64,y==0 -> sort block. dyn smem 64KB.
// ---------------------------------------------------------------------------
__global__ __launch_bounds__(256)
void qkv_sort_kernel(const float* __restrict__ inp, const int* __restrict__ pos,
                     const float* __restrict__ Wq, const float* __restrict__ bq,
                     const float* __restrict__ Wk, const float* __restrict__ bk,
                     const float* __restrict__ Wv, const float* __restrict__ bv)
{
    extern __shared__ float sm[];
    if (blockIdx.x == 64) {
        if (blockIdx.y == 0) sort_block(pos, (int*)sm);
        return;
    }

    float* As = sm;               // 64 x 128
    float* Bs = sm + 64 * PDIM;   // 128 x 64

    const int which = blockIdx.y >> 1, colh = blockIdx.y & 1;
    const float* W = (which == 0) ? Wq : (which == 1) ? Wk : Wv;
    const float* b = (which == 0) ? bq : (which == 1) ? bk : bv;
    float* outp = g_QKV[which];

    const int row0 = blockIdx.x * 64, col0 = colh * 64;
    const int tid = threadIdx.x;

    const float4* inp4 = (const float4*)(inp + row0 * PDIM);
    const float4* W4 = (const float4*)W;
    for (int i = tid; i < 2048; i += 256) ((float4*)As)[i] = inp4[i];
    for (int i = tid; i < 2048; i += 256) {
        int k = i >> 4, c4 = i & 15;
        ((float4*)Bs)[k * 16 + c4] = W4[k * 32 + colh * 16 + c4];
    }
    __syncthreads();

    const int tx = tid & 15, ty = tid >> 4;   // rows ty*4..+3, cols col0+tx*4..+3

    unsigned long long acc[4][2];
#pragma unroll
    for (int i = 0; i < 4; i++) { acc[i][0] = 0ull; acc[i][1] = 0ull; }

    const ulonglong2* Bs2 = (const ulonglong2*)Bs;
#pragma unroll 2
    for (int k = 0; k < PDIM; k++) {
        ulonglong2 bb = Bs2[k * 16 + tx];
#pragma unroll
        for (int i = 0; i < 4; i++) {
            float a = As[(ty * 4 + i) * PDIM + k];
            unsigned long long aa = f2pk(a, a);
            acc[i][0] = ffma2(aa, bb.x, acc[i][0]);
            acc[i][1] = ffma2(aa, bb.y, acc[i][1]);
        }
    }

    float4 bias = ((const float4*)(b + col0))[tx];
#pragma unroll
    for (int i = 0; i < 4; i++) {
        float x0, x1, x2, x3;
        f2un(acc[i][0], x0, x1);
        f2un(acc[i][1], x2, x3);
        float4 r = make_float4(x0 + bias.x, x1 + bias.y, x2 + bias.z, x3 + bias.w);
        *(float4*)&outp[(row0 + ty * 4 + i) * PDIM + col0 + tx * 4] = r;
    }
}

// ---------------------------------------------------------------------------
// Attention: per (seg, head, 64-query tile). 256 threads, 2 blocks/SM.
// GEMM1 S=Q*K^T (f32x2 pairs along q) -> softmax (inv deferred) -> GEMM2 O=P*V.
// SMEM: KT[32][192] Vs[192][32] QsT[32][64] S[192][66] sInv[64] = 105.8KB
// ---------------------------------------------------------------------------
__global__ __launch_bounds__(256, 2)
void attn_kernel(float* __restrict__ out)
{
    extern __shared__ float smf[];
    float* KT   = smf;                        // 32*192
    float* Vs   = KT + EDIM * KCAP;           // 192*32
    float* QsT  = Vs + KCAP * EDIM;           // 32*64
    float* S    = QsT + EDIM * QT;            // 192*66
    float* sInv = S + KCAP * SSTR;            // 64

    const int seg = blockIdx.x, h = blockIdx.y, z = blockIdx.z;
    const int off = g_off[seg];
    const int cnt = g_cnt[seg];
    const int tid = threadIdx.x, lane = tid & 31, w = tid >> 5;

    const float* Q = g_QKV[0];
    const float* K = g_QKV[1];
    const float* V = g_QKV[2];

    if (cnt > KCAP) {
        // fallback (prob ~0 for this input): streaming online softmax, all z cooperate
        int gw = z * 8 + w;
        for (int qi = gw; qi < cnt; qi += QTILES * 8) {
            int t = g_idx[off + qi];
            float qv = Q[t * PDIM + h * EDIM + lane] * QSCALE;
            float m = NEGINF, l = 0.f, a = 0.f;
            for (int j = 0; j < cnt; j++) {
                int tj = g_idx[off + j];
                float s = qv * K[tj * PDIM + h * EDIM + lane];
#pragma unroll
                for (int d = 16; d; d >>= 1) s += __shfl_xor_sync(0xffffffffu, s, d);
                float mn  = fmaxf(m, s);
                float cor = __expf(m - mn);
                float pj  = __expf(s - mn);
                l = l * cor + pj;
                a = a * cor + pj * V[tj * PDIM + h * EDIM + lane];
                m = mn;
            }
            out[t * PDIM + h * EDIM + lane] = a / l;
        }
        return;
    }

    const int nq = min(QT, cnt - z * QT);
    if (nq <= 0) return;

    // gather K (transposed) + V for all cnt keys
    for (int i = tid; i < cnt * 8; i += 256) {
        int r = i >> 3, c = i & 7;
        int t = g_idx[off + r];
        float4 kf = *(const float4*)(K + t * PDIM + h * EDIM + c * 4);
        KT[(c * 4 + 0) * KCAP + r] = kf.x;
        KT[(c * 4 + 1) * KCAP + r] = kf.y;
        KT[(c * 4 + 2) * KCAP + r] = kf.z;
        KT[(c * 4 + 3) * KCAP + r] = kf.w;
        *(float4*)&Vs[r * EDIM + c * 4] = *(const float4*)(V + t * PDIM + h * EDIM + c * 4);
    }
    // gather Q tile (transposed, pre-scaled)
    for (int i = tid; i < nq * 8; i += 256) {
        int q = i >> 3, c = i & 7;
        int t = g_idx[off + z * QT + q];
        float4 qf = *(const float4*)(Q + t * PDIM + h * EDIM + c * 4);
        QsT[(c * 4 + 0) * QT + q] = qf.x * QSCALE;
        QsT[(c * 4 + 1) * QT + q] = qf.y * QSCALE;
        QsT[(c * 4 + 2) * QT + q] = qf.z * QSCALE;
        QsT[(c * 4 + 3) * QT + q] = qf.w * QSCALE;
    }
    __syncthreads();

    const int tx = tid & 15, ty = tid >> 4;   // queries ty*4..+3 (2 pairs), keys tx+16r

    // ---- GEMM1: S[j][q] = sum_e Q[q][e]*K[j][e]  (pairs along q) ----
    {
        unsigned long long acc[2][12];
#pragma unroll
        for (int r = 0; r < 12; r++) { acc[0][r] = 0ull; acc[1][r] = 0ull; }

#pragma unroll 2
        for (int e = 0; e < EDIM; e++) {
            const float* KTe = KT + e * KCAP + tx;
            float2 qa = *(const float2*)&QsT[e * QT + ty * 4];
            float2 qb = *(const float2*)&QsT[e * QT + ty * 4 + 2];
            unsigned long long qpa = f2pk(qa.x, qa.y);
            unsigned long long qpb = f2pk(qb.x, qb.y);
#pragma unroll
            for (int r = 0; r < 12; r++) {
                float kv = KTe[16 * r];
                unsigned long long kk = f2pk(kv, kv);
                acc[0][r] = ffma2(qpa, kk, acc[0][r]);
                acc[1][r] = ffma2(qpb, kk, acc[1][r]);
            }
        }
#pragma unroll
        for (int r = 0; r < 12; r++) {
            int j = tx + 16 * r;
            *(unsigned long long*)&S[j * SSTR + ty * 4]     = acc[0][r];
            *(unsigned long long*)&S[j * SSTR + ty * 4 + 2] = acc[1][r];
        }
    }
    __syncthreads();

    // ---- softmax over keys per query (normalization deferred to epilogue) ----
    for (int q = w; q < nq; q += 8) {
        float m = NEGINF;
        for (int j = lane; j < cnt; j += 32) m = fmaxf(m, S[j * SSTR + q]);
#pragma unroll
        for (int d = 16; d; d >>= 1) m = fmaxf(m, __shfl_xor_sync(0xffffffffu, m, d));
        float sum = 0.f;
        for (int j = lane; j < cnt; j += 32) {
            float p = __expf(S[j * SSTR + q] - m);
            S[j * SSTR + q] = p;
            sum += p;
        }
#pragma unroll
        for (int d = 16; d; d >>= 1) sum += __shfl_xor_sync(0xffffffffu, sum, d);
        if (lane == 0) sInv[q] = 1.f / sum;
    }
    __syncthreads();

    // ---- GEMM2: O[q][e] = sum_j P[j][q]*V[j][e]  (pairs along q; e = tx*2, tx*2+1) ----
    unsigned long long o00 = 0ull, o01 = 0ull, o10 = 0ull, o11 = 0ull;
#pragma unroll 4
    for (int j = 0; j < cnt; j++) {
        unsigned long long ppa = *(const unsigned long long*)&S[j * SSTR + ty * 4];
        unsigned long long ppb = *(const unsigned long long*)&S[j * SSTR + ty * 4 + 2];
        float2 v = *(const float2*)&Vs[j * EDIM + tx * 2];
        unsigned long long v0 = f2pk(v.x, v.x);
        unsigned long long v1 = f2pk(v.y, v.y);
        o00 = ffma2(ppa, v0, o00);
        o01 = ffma2(ppa, v1, o01);
        o10 = ffma2(ppb, v0, o10);
        o11 = ffma2(ppb, v1, o11);
    }

    // ---- epilogue: scale by 1/sum, scatter to original rows ----
    {
        int e0 = h * EDIM + tx * 2;
        float a0e0, a1e0, a0e1, a1e1;
        f2un(o00, a0e0, a1e0);
        f2un(o01, a0e1, a1e1);
        int qa = ty * 4, qb = ty * 4 + 1;
        if (qa < nq) {
            int t = g_idx[off + z * QT + qa]; float iv = sInv[qa];
            out[t * PDIM + e0] = a0e0 * iv; out[t * PDIM + e0 + 1] = a0e1 * iv;
        }
        if (qb < nq) {
            int t = g_idx[off + z * QT + qb]; float iv = sInv[qb];
            out[t * PDIM + e0] = a1e0 * iv; out[t * PDIM + e0 + 1] = a1e1 * iv;
        }
        f2un(o10, a0e0, a1e0);
        f2un(o11, a0e1, a1e1);
        qa = ty * 4 + 2; qb = ty * 4 + 3;
        if (qa < nq) {
            int t = g_idx[off + z * QT + qa]; float iv = sInv[qa];
            out[t * PDIM + e0] = a0e0 * iv; out[t * PDIM + e0 + 1] = a0e1 * iv;
        }
        if (qb < nq) {
            int t = g_idx[off + z * QT + qb]; float iv = sInv[qb];
            out[t * PDIM + e0] = a1e0 * iv; out[t * PDIM + e0 + 1] = a1e1 * iv;
        }
    }
}

// ---------------------------------------------------------------------------
extern "C" void kernel_launch(void* const* d_in, const int* in_sizes, int n_in,
                              void* d_out, int out_size)
{
    const float* inp = (const float*)d_in[0];
    const int*   pos = (const int*)  d_in[1];
    const float* Wq  = (const float*)d_in[2];
    const float* bq  = (const float*)d_in[3];
    const float* Wk  = (const float*)d_in[4];
    const float* bk  = (const float*)d_in[5];
    const float* Wv  = (const float*)d_in[6];
    const float* bv  = (const float*)d_in[7];
    float* out = (float*)d_out;

    const int qkv_smem  = (64 * PDIM + PDIM * 64) * 4;                           // 65536
    const int attn_smem = (EDIM * KCAP + KCAP * EDIM + EDIM * QT
                           + KCAP * SSTR + QT) * 4;                              // 108288

    cudaFuncSetAttribute(qkv_sort_kernel, cudaFuncAttributeMaxDynamicSharedMemorySize, qkv_smem);
    cudaFuncSetAttribute(attn_kernel,     cudaFuncAttributeMaxDynamicSharedMemorySize, attn_smem);

    qkv_sort_kernel<<<dim3(65, 6), 256, qkv_smem>>>(inp, pos, Wq, bq, Wk, bk, Wv, bv);
    attn_kernel<<<dim3(NSEGS, HEADS, QTILES), 256, attn_smem>>>(out);
}